// round 13
// baseline (speedup 1.0000x reference)
#include <cuda_runtime.h>
#include <cuda_bf16.h>

#define STEPS 16

// ---- lifted-rotation coefficient tables -----------------------------------
// Scaled coords: x_true = d ∘ x̂ ; per pair (a,b):
//   â' = â − β·b̂ ;  b̂' = α·â + b̂            (8 FMA, β/α complex)
//   β = (st/ct)·(d_b/d_a), α = (st/ct)·(d_a/d_b)
//   d_a' = w·ct·d_a, d_b' = ct·d_b            (w = sp + i·cp)
// Table layout identical to R12: gE/gO[s][c][j][L] = (βr, βi, αr, αi),
// gOL[s][c][L] = (αr, αi) of left-boundary pair 128c+4L-1.
// Nonexistent pairs -> zeros (exact identity).
// g_om[e] = ω_e · d_e(final)  (epilogue complex multiplier).
__device__ float4 gE [STEPS][4][4][32];
__device__ float4 gO [STEPS][4][4][32];
__device__ float2 gOL[STEPS][4][32];
__device__ float2 g_om[1024];

// d trajectory: state BEFORE global sweep sigma (0..31), [32] = final.
// d = phase (unit complex) * exp(lg).
__device__ float2 d_ph[33][1024];
__device__ float  d_lg[33][1024];

__device__ __forceinline__ float safe_ct(float ct) {
    float a = fabsf(ct);
    return (a < 1e-30f) ? copysignf(1e-30f, ct) : ct;
}

// ---- precompute A: per-element d walk (fully parallel over elements) ------
__global__ void eunn_pre_dwalk(const float* __restrict__ et,
                               const float* __restrict__ ot,
                               const float* __restrict__ ep,
                               const float* __restrict__ op)
{
    int e = blockIdx.x * blockDim.x + threadIdx.x;   // 0..1023
    if (e >= 1024) return;

    float2 ph = make_float2(1.f, 0.f);
    float  lg = 0.f;

    for (int s = 0; s < STEPS; s++) {
        // ----- even sweep (sigma = 2s): pair p = e>>1; e even = 'a' -----
        d_ph[2*s][e] = ph;  d_lg[2*s][e] = lg;
        {
            int p = e >> 1;
            float st, ct;
            __sincosf(et[s * 512 + p], &st, &ct);
            ct = safe_ct(ct);
            float sgn = (ct < 0.f) ? -1.f : 1.f;
            lg += __logf(fabsf(ct));
            if ((e & 1) == 0) {            // a-role: phase *= sgn * w
                float sp, cp;
                __sincosf(ep[s * 512 + p], &sp, &cp);
                float nr = sp * ph.x - cp * ph.y;
                float ni = sp * ph.y + cp * ph.x;
                ph = make_float2(sgn * nr, sgn * ni);
            } else {                       // b-role: phase *= sgn
                ph = make_float2(sgn * ph.x, sgn * ph.y);
            }
        }
        // ----- odd sweep (sigma = 2s+1): e=0,1023 identity -----
        d_ph[2*s+1][e] = ph;  d_lg[2*s+1][e] = lg;
        if (e != 0 && e != 1023) {
            int q; bool arole;
            if (e & 1) { q = (e - 1) >> 1; arole = true;  }
            else       { q = (e >> 1) - 1; arole = false; }
            float st, ct;
            __sincosf(ot[s * 511 + q], &st, &ct);    // NB stride 511
            ct = safe_ct(ct);
            float sgn = (ct < 0.f) ? -1.f : 1.f;
            lg += __logf(fabsf(ct));
            if (arole) {
                float sp, cp;
                __sincosf(op[s * 511 + q], &sp, &cp);
                float nr = sp * ph.x - cp * ph.y;
                float ni = sp * ph.y + cp * ph.x;
                ph = make_float2(sgn * nr, sgn * ni);
            } else {
                ph = make_float2(sgn * ph.x, sgn * ph.y);
            }
        }
    }
    d_ph[32][e] = ph;  d_lg[32][e] = lg;
}

// ---- precompute B: per-(sweep,pair) coefficients + epilogue table ---------
__device__ __forceinline__ float4 lift_coeffs(float theta, int i, int j, int sigma)
{
    float st, ct;
    __sincosf(theta, &st, &ct);
    ct = safe_ct(ct);
    float t = st / ct;
    float2 pi_ = d_ph[sigma][i], pj_ = d_ph[sigma][j];
    float  gi  = d_lg[sigma][i], gj  = d_lg[sigma][j];
    // unit phase ratio pj/pi = pj * conj(pi)
    float prr = pj_.x * pi_.x + pj_.y * pi_.y;
    float pri = pj_.y * pi_.x - pj_.x * pi_.y;
    float m    = __expf(gj - gi);   // |dj|/|di|
    float minv = __expf(gi - gj);
    // beta = t*m*(prr,pri) ; alpha = t*minv*(prr,-pri)
    return make_float4(t * m * prr,  t * m * pri,
                       t * minv * prr, -t * minv * pri);
}

__global__ void eunn_pre_tables(const float* __restrict__ omega,
                                const float* __restrict__ et,
                                const float* __restrict__ ot)
{
    int idx = blockIdx.x * blockDim.x + threadIdx.x;
    if (idx < 8192) {
        // even pair p, step s, global sweep 2s ; i=2p (a), j=2p+1 (b)
        int s = idx >> 9, p = idx & 511;
        int c = p >> 7, w = p & 127, L = w >> 2, jj = w & 3;
        gE[s][c][jj][L] = lift_coeffs(et[s * 512 + p], 2 * p, 2 * p + 1, 2 * s);
    } else if (idx < 16384) {
        // odd pair q, global sweep 2s+1 ; i=2q+1 (a), j=2q+2 (b)
        int t = idx - 8192;
        int s = t >> 9, q = t & 511;
        if (q < 511) {
            int c = q >> 7, w = q & 127, L = w >> 2, jj = w & 3;
            float4 C = lift_coeffs(ot[s * 511 + q], 2 * q + 1, 2 * q + 2, 2 * s + 1);
            gO[s][c][jj][L] = C;
            if (jj == 3) {
                // also the LEFT-boundary (alpha) entry of the next lane
                int q1 = q + 1;
                gOL[s][q1 >> 7][(q1 & 127) >> 2] = make_float2(C.z, C.w);
            }
        } else {
            gO[s][3][3][31] = make_float4(0.f, 0.f, 0.f, 0.f);
            gOL[s][0][0]    = make_float2(0.f, 0.f);
        }
    } else if (idx < 17408) {
        // epilogue: g_om[e] = omega_phase * d_final
        int e = idx - 16384;
        float sn, cs;
        __sincosf(omega[e], &sn, &cs);
        float2 ph = d_ph[32][e];
        float  sc = __expf(d_lg[32][e]);
        g_om[e] = make_float2(sc * (cs * ph.x - sn * ph.y),
                              sc * (cs * ph.y + sn * ph.x));
    }
}

// 8-FMA lifted rotation; C = (br, bi, ar, ai) meaning beta, alpha
#define LROT(Ar, Ai, Br, Bi, C)                                        \
    do {                                                               \
        float _ar = (Ar), _ai = (Ai), _br = (Br), _bi = (Bi);          \
        (Ar) = fmaf(-(C).x, _br, fmaf( (C).y, _bi, _ar));              \
        (Ai) = fmaf(-(C).x, _bi, fmaf(-(C).y, _br, _ai));              \
        (Br) = fmaf( (C).z, _ar, fmaf(-(C).w, _ai, _br));              \
        (Bi) = fmaf( (C).z, _ai, fmaf( (C).w, _ar, _bi));              \
    } while (0)

// 16-step scan for R rows (structure identical to R12, which passed).
template<int R>
__device__ __forceinline__ void eunn_steps(
    float (&xr)[4][8], float (&xi)[4][8],
    float (&sE0)[2][2][4][4][2], float (&sE7)[2][2][4][4][2],
    int lane, int c, int g)
{
    float4 E0 = gE[0][c][0][lane], E1 = gE[0][c][1][lane];
    float4 E2 = gE[0][c][2][lane], E3 = gE[0][c][3][lane];

#pragma unroll 1
    for (int s = 0; s < STEPS; s++) {
        int par = s & 1;

        float4 O0 = gO[s][c][0][lane], O1 = gO[s][c][1][lane];
        float4 O2 = gO[s][c][2][lane], O3 = gO[s][c][3][lane];
        float2 OL = gOL[s][c][lane];

        // ---------------- even sweep: 4 lane-internal pairs ----------------
#pragma unroll
        for (int r = 0; r < R; r++) {
            LROT(xr[r][0], xi[r][0], xr[r][1], xi[r][1], E0);
            LROT(xr[r][2], xi[r][2], xr[r][3], xi[r][3], E1);
            LROT(xr[r][4], xi[r][4], xr[r][5], xi[r][5], E2);
            LROT(xr[r][6], xi[r][6], xr[r][7], xi[r][7], E3);
        }

        // publish post-even slice edges
        if (lane == 0) {
#pragma unroll
            for (int r = 0; r < R; r++) {
                sE0[par][g][c][r][0] = xr[r][0];
                sE0[par][g][c][r][1] = xi[r][0];
            }
        }
        if (lane == 31) {
#pragma unroll
            for (int r = 0; r < R; r++) {
                sE7[par][g][c][r][0] = xr[r][7];
                sE7[par][g][c][r][1] = xi[r][7];
            }
        }
        asm volatile("bar.sync %0, 128;" :: "r"(g + 1) : "memory");

        // prefetch NEXT step's even coefficients (hidden under odd sweep)
        int sn = (s + 1 < STEPS) ? s + 1 : s;
        E0 = gE[sn][c][0][lane]; E1 = gE[sn][c][1][lane];
        E2 = gE[sn][c][2][lane]; E3 = gE[sn][c][3][lane];

        // ---------------- odd sweep ----------------
        bool smR = (lane == 31) && (c < 3);
        bool smL = (lane == 0)  && (c > 0);
#pragma unroll
        for (int r = 0; r < R; r++) {
            // neighbor pre-odd edges: right e0, left e7
            float nbr = __shfl_down_sync(0xffffffffu, xr[r][0], 1);
            float nbi = __shfl_down_sync(0xffffffffu, xi[r][0], 1);
            float lar = __shfl_up_sync  (0xffffffffu, xr[r][7], 1);
            float lai = __shfl_up_sync  (0xffffffffu, xi[r][7], 1);
            if (smR) { nbr = sE0[par][g][c + 1][r][0]; nbi = sE0[par][g][c + 1][r][1]; }
            if (smL) { lar = sE7[par][g][c - 1][r][0]; lai = sE7[par][g][c - 1][r][1]; }

            // internal pairs — fill shuffle latency
            LROT(xr[r][1], xi[r][1], xr[r][2], xi[r][2], O0);
            LROT(xr[r][3], xi[r][3], xr[r][4], xi[r][4], O1);
            LROT(xr[r][5], xi[r][5], xr[r][6], xi[r][6], O2);

            // boundary a'-half: e7' = e7 − beta * (right neighbor pre-odd e0)
            xr[r][7] = fmaf(-O3.x, nbr, fmaf( O3.y, nbi, xr[r][7]));
            xi[r][7] = fmaf(-O3.x, nbi, fmaf(-O3.y, nbr, xi[r][7]));

            // boundary b'-half: e0' = e0 + alpha * (left neighbor pre-odd e7)
            xr[r][0] = fmaf(OL.x, lar, fmaf(-OL.y, lai, xr[r][0]));
            xi[r][0] = fmaf(OL.x, lai, fmaf( OL.y, lar, xi[r][0]));
        }
    }
}

// One single wave: 296 CTAs; each g-group (4 slice-warps) owns 7 rows
// (last 48 groups: 6): batch A = 4 rows then batch B = 3 (or 2, masked).
__global__ void __launch_bounds__(256, 2)
eunn_main(const float* __restrict__ x, float* __restrict__ out)
{
    __shared__ float sE0[2][2][4][4][2];   // [parity][g][slice][row][re/im]
    __shared__ float sE7[2][2][4][4][2];

    int lane  = threadIdx.x & 31;
    int wblk  = threadIdx.x >> 5;
    int c     = wblk & 3;
    int g     = wblk >> 2;
    int ebase = c * 256 + lane * 8;

    int gid = blockIdx.x * 2 + g;          // 0..591
    int row0, nB;
    if (gid < 544) { row0 = gid * 7;                  nB = 3; }
    else           { row0 = 3808 + (gid - 544) * 6;   nB = 2; }

    const float4* omv = (const float4*)g_om;
    float xr[4][8], xi[4][8];

    // =========================== batch A: 4 rows ===========================
#pragma unroll
    for (int r = 0; r < 4; r++) {
        const float4* p4 = (const float4*)(x + (size_t)(row0 + r) * 2048 + ebase * 2);
#pragma unroll
        for (int i = 0; i < 4; i++) {
            float4 v = __ldg(&p4[i]);
            xr[r][2*i] = v.x; xi[r][2*i] = v.y; xr[r][2*i+1] = v.z; xi[r][2*i+1] = v.w;
        }
    }

    eunn_steps<4>(xr, xi, sE0, sE7, lane, c, g);

#pragma unroll
    for (int r = 0; r < 4; r++) {
        float4* o4 = (float4*)(out + (size_t)(row0 + r) * 2048 + ebase * 2);
#pragma unroll
        for (int i = 0; i < 4; i++) {
            float4 m = omv[(ebase >> 1) + i];
            float r0 = xr[r][2*i]   * m.x - xi[r][2*i]   * m.y;
            float i0 = xr[r][2*i]   * m.y + xi[r][2*i]   * m.x;
            float r1 = xr[r][2*i+1] * m.z - xi[r][2*i+1] * m.w;
            float i1 = xr[r][2*i+1] * m.w + xi[r][2*i+1] * m.z;
            o4[i] = make_float4(r0, i0, r1, i1);
        }
    }

    // ========================= batch B: nB (2-3) rows ======================
    int rowB = row0 + 4;
#pragma unroll
    for (int r = 0; r < 3; r++) {
        int rr = rowB + (r < nB ? r : nB - 1);   // clamp: duplicate last valid row
        const float4* p4 = (const float4*)(x + (size_t)rr * 2048 + ebase * 2);
#pragma unroll
        for (int i = 0; i < 4; i++) {
            float4 v = __ldg(&p4[i]);
            xr[r][2*i] = v.x; xi[r][2*i] = v.y; xr[r][2*i+1] = v.z; xi[r][2*i+1] = v.w;
        }
    }

    eunn_steps<3>(xr, xi, sE0, sE7, lane, c, g);

#pragma unroll
    for (int r = 0; r < 3; r++) {
        if (r < nB) {
            float4* o4 = (float4*)(out + (size_t)(rowB + r) * 2048 + ebase * 2);
#pragma unroll
            for (int i = 0; i < 4; i++) {
                float4 m = omv[(ebase >> 1) + i];
                float r0 = xr[r][2*i]   * m.x - xi[r][2*i]   * m.y;
                float i0 = xr[r][2*i]   * m.y + xi[r][2*i]   * m.x;
                float r1 = xr[r][2*i+1] * m.z - xi[r][2*i+1] * m.w;
                float i1 = xr[r][2*i+1] * m.w + xi[r][2*i+1] * m.z;
                o4[i] = make_float4(r0, i0, r1, i1);
            }
        }
    }
}

extern "C" void kernel_launch(void* const* d_in, const int* in_sizes, int n_in,
                              void* d_out, int out_size)
{
    const float* x     = (const float*)d_in[0];
    const float* omega = (const float*)d_in[1];
    const float* et    = (const float*)d_in[2];
    const float* ot    = (const float*)d_in[3];
    const float* ep    = (const float*)d_in[4];
    const float* op    = (const float*)d_in[5];

    eunn_pre_dwalk <<<8, 128>>>(et, ot, ep, op);           // 1024 d-walks
    eunn_pre_tables<<<68, 256>>>(omega, et, ot);           // 17408 threads

    eunn_main<<<296, 256>>>(x, (float*)d_out);             // single wave
}